// round 1
// baseline (speedup 1.0000x reference)
#include <cuda_runtime.h>
#include <cstdint>

#define TT 4096   // tokens = B*S
#define HH 1024   // hidden
#define FF 4096   // ffn
#define NE 8      // experts

#define BM 128
#define BN 64
#define BK 32
#define TILES_M (TT / BM)   // 32 per expert (worst case)

// scratch (device globals: allowed; no runtime allocation)
__device__ float g_mid[(size_t)TT * FF];   // 64 MB intermediate (perm order)
__device__ int   g_perm[TT];
__device__ int   g_expert_of[TT];
__device__ float g_maxprob[TT];
__device__ int   g_cnt[NE];
__device__ int   g_off[NE + 1];
__device__ int   g_cur[NE];

__device__ __forceinline__ float to_tf32(float x) {
    uint32_t u;
    asm("cvt.rna.tf32.f32 %0, %1;" : "=r"(u) : "f"(x));
    return __uint_as_float(u);
}

__device__ __forceinline__ float gelu_exact(float v) {
    return 0.5f * v * (1.0f + erff(v * 0.7071067811865476f));
}

__global__ void init_kernel() {
    if (threadIdx.x < NE) g_cnt[threadIdx.x] = 0;
}

// One warp per token: logits = x @ Wr + br; argmax + sigmoid(max); histogram.
__global__ void router_kernel(const float* __restrict__ x,
                              const float* __restrict__ Wr,
                              const float* __restrict__ br) {
    int warp = (blockIdx.x * blockDim.x + threadIdx.x) >> 5;
    int lane = threadIdx.x & 31;
    if (warp >= TT) return;
    const float* xr = x + (size_t)warp * HH;
    float acc[NE];
#pragma unroll
    for (int e = 0; e < NE; e++) acc[e] = 0.f;
    for (int i = lane; i < HH; i += 32) {
        float xv = xr[i];
        const float4* w4 = reinterpret_cast<const float4*>(Wr + i * NE);
        float4 w0 = w4[0], w1 = w4[1];
        acc[0] += xv * w0.x; acc[1] += xv * w0.y;
        acc[2] += xv * w0.z; acc[3] += xv * w0.w;
        acc[4] += xv * w1.x; acc[5] += xv * w1.y;
        acc[6] += xv * w1.z; acc[7] += xv * w1.w;
    }
#pragma unroll
    for (int e = 0; e < NE; e++) {
#pragma unroll
        for (int o = 16; o > 0; o >>= 1)
            acc[e] += __shfl_xor_sync(0xffffffffu, acc[e], o);
    }
    if (lane == 0) {
        float best = acc[0] + br[0]; int bi = 0;
#pragma unroll
        for (int e = 1; e < NE; e++) {
            float v = acc[e] + br[e];
            if (v > best) { best = v; bi = e; }
        }
        g_expert_of[warp] = bi;
        g_maxprob[warp]   = 1.0f / (1.0f + expf(-best));
        atomicAdd(&g_cnt[bi], 1);
    }
}

__global__ void scan_kernel() {
    if (threadIdx.x == 0) {
        int off = 0;
        for (int e = 0; e < NE; e++) {
            g_off[e] = off; g_cur[e] = off; off += g_cnt[e];
        }
        g_off[NE] = off;
    }
}

__global__ void perm_kernel() {
    int t = blockIdx.x * blockDim.x + threadIdx.x;
    if (t < TT) {
        int e = g_expert_of[t];
        int slot = atomicAdd(&g_cur[e], 1);
        g_perm[slot] = t;
    }
}

// ---------------------------------------------------------------------------
// Grouped GEMM 1:  mid[perm_row] = gelu( x[token] @ W1[e] )
// BM=128 x BN=64, BK=32, 256 threads (8 warps, 4x2), warp tile 32x32,
// mma.sync.m16n8k8 tf32.
// ---------------------------------------------------------------------------
__global__ __launch_bounds__(256) void fc1_kernel(const float* __restrict__ x,
                                                  const float* __restrict__ W1) {
    __shared__ float As[BM][36];   // conflict-free (stride 36)
    __shared__ float Bs[BK][72];   // conflict-free (stride 72)

    int e  = blockIdx.x >> 5;      // / TILES_M
    int mt = blockIdx.x & 31;
    int cnt = g_off[e + 1] - g_off[e];
    if (mt * BM >= cnt) return;
    int base = g_off[e] + mt * BM;
    int n0 = blockIdx.y * BN;
    const float* Be = W1 + (size_t)e * HH * FF;

    int tid  = threadIdx.x;
    int lane = tid & 31, warp = tid >> 5;
    int wm = warp >> 1, wn = warp & 1;
    int m_base = wm * 32, n_base = wn * 32;

    // A load assignment: 2 threads per row, 16 floats each
    int a_row = tid >> 1;
    int a_c0  = (tid & 1) * 16;
    int r     = mt * BM + a_row;
    int gtok  = (r < cnt) ? g_perm[base + a_row] : 0;
    const float* arow_ptr = x + (size_t)gtok * HH;

    float acc[2][4][4];
#pragma unroll
    for (int i = 0; i < 2; i++)
#pragma unroll
        for (int j = 0; j < 4; j++)
#pragma unroll
            for (int k = 0; k < 4; k++) acc[i][j][k] = 0.f;

    for (int kb = 0; kb < HH; kb += BK) {
        __syncthreads();
#pragma unroll
        for (int j = 0; j < 4; j++) {
            float4 v = *reinterpret_cast<const float4*>(arow_ptr + kb + a_c0 + j * 4);
            As[a_row][a_c0 + j * 4 + 0] = to_tf32(v.x);
            As[a_row][a_c0 + j * 4 + 1] = to_tf32(v.y);
            As[a_row][a_c0 + j * 4 + 2] = to_tf32(v.z);
            As[a_row][a_c0 + j * 4 + 3] = to_tf32(v.w);
        }
#pragma unroll
        for (int j = 0; j < 2; j++) {
            int f = tid + j * 256;
            int brow = f >> 4;
            int bc   = (f & 15) * 4;
            float4 v = *reinterpret_cast<const float4*>(
                Be + (size_t)(kb + brow) * FF + n0 + bc);
            Bs[brow][bc + 0] = to_tf32(v.x);
            Bs[brow][bc + 1] = to_tf32(v.y);
            Bs[brow][bc + 2] = to_tf32(v.z);
            Bs[brow][bc + 3] = to_tf32(v.w);
        }
        __syncthreads();

#pragma unroll
        for (int ks = 0; ks < 4; ks++) {
            int k = ks * 8;
            uint32_t a[2][4], b[4][2];
#pragma unroll
            for (int mi = 0; mi < 2; mi++) {
                int r0 = m_base + mi * 16 + (lane >> 2);
                int c0 = k + (lane & 3);
                a[mi][0] = __float_as_uint(As[r0][c0]);
                a[mi][1] = __float_as_uint(As[r0 + 8][c0]);
                a[mi][2] = __float_as_uint(As[r0][c0 + 4]);
                a[mi][3] = __float_as_uint(As[r0 + 8][c0 + 4]);
            }
#pragma unroll
            for (int ni = 0; ni < 4; ni++) {
                int col = n_base + ni * 8 + (lane >> 2);
                int kr  = k + (lane & 3);
                b[ni][0] = __float_as_uint(Bs[kr][col]);
                b[ni][1] = __float_as_uint(Bs[kr + 4][col]);
            }
#pragma unroll
            for (int mi = 0; mi < 2; mi++)
#pragma unroll
                for (int ni = 0; ni < 4; ni++) {
                    asm volatile(
                        "mma.sync.aligned.m16n8k8.row.col.f32.tf32.tf32.f32 "
                        "{%0,%1,%2,%3}, {%4,%5,%6,%7}, {%8,%9}, {%0,%1,%2,%3};\n"
                        : "+f"(acc[mi][ni][0]), "+f"(acc[mi][ni][1]),
                          "+f"(acc[mi][ni][2]), "+f"(acc[mi][ni][3])
                        : "r"(a[mi][0]), "r"(a[mi][1]), "r"(a[mi][2]), "r"(a[mi][3]),
                          "r"(b[ni][0]), "r"(b[ni][1]));
                }
        }
    }

    // epilogue: gelu -> g_mid (perm order rows)
#pragma unroll
    for (int mi = 0; mi < 2; mi++) {
#pragma unroll
        for (int half = 0; half < 2; half++) {
            int row = m_base + mi * 16 + half * 8 + (lane >> 2);
            if (mt * BM + row < cnt) {
                float* mp = g_mid + (size_t)(base + row) * FF + n0;
#pragma unroll
                for (int ni = 0; ni < 4; ni++) {
                    int c = n_base + ni * 8 + (lane & 3) * 2;
                    mp[c]     = gelu_exact(acc[mi][ni][half * 2 + 0]);
                    mp[c + 1] = gelu_exact(acc[mi][ni][half * 2 + 1]);
                }
            }
        }
    }
}

// ---------------------------------------------------------------------------
// Grouped GEMM 2:  out[token] = (mid[perm_row] @ W2[e]) * maxprob[token]
// ---------------------------------------------------------------------------
__global__ __launch_bounds__(256) void fc2_kernel(const float* __restrict__ W2,
                                                  float* __restrict__ out) {
    __shared__ float As[BM][36];
    __shared__ float Bs[BK][72];

    int e  = blockIdx.x >> 5;
    int mt = blockIdx.x & 31;
    int cnt = g_off[e + 1] - g_off[e];
    if (mt * BM >= cnt) return;
    int base = g_off[e] + mt * BM;
    int n0 = blockIdx.y * BN;
    const float* Be = W2 + (size_t)e * FF * HH;

    int tid  = threadIdx.x;
    int lane = tid & 31, warp = tid >> 5;
    int wm = warp >> 1, wn = warp & 1;
    int m_base = wm * 32, n_base = wn * 32;

    int a_row = tid >> 1;
    int a_c0  = (tid & 1) * 16;
    int midrow = base + a_row;
    if (midrow > TT - 1) midrow = TT - 1;   // clamp (only hit for invalid rows)
    const float* arow_ptr = g_mid + (size_t)midrow * FF;

    float acc[2][4][4];
#pragma unroll
    for (int i = 0; i < 2; i++)
#pragma unroll
        for (int j = 0; j < 4; j++)
#pragma unroll
            for (int k = 0; k < 4; k++) acc[i][j][k] = 0.f;

    for (int kb = 0; kb < FF; kb += BK) {
        __syncthreads();
#pragma unroll
        for (int j = 0; j < 4; j++) {
            float4 v = *reinterpret_cast<const float4*>(arow_ptr + kb + a_c0 + j * 4);
            As[a_row][a_c0 + j * 4 + 0] = to_tf32(v.x);
            As[a_row][a_c0 + j * 4 + 1] = to_tf32(v.y);
            As[a_row][a_c0 + j * 4 + 2] = to_tf32(v.z);
            As[a_row][a_c0 + j * 4 + 3] = to_tf32(v.w);
        }
#pragma unroll
        for (int j = 0; j < 2; j++) {
            int f = tid + j * 256;
            int brow = f >> 4;
            int bc   = (f & 15) * 4;
            float4 v = *reinterpret_cast<const float4*>(
                Be + (size_t)(kb + brow) * HH + n0 + bc);
            Bs[brow][bc + 0] = to_tf32(v.x);
            Bs[brow][bc + 1] = to_tf32(v.y);
            Bs[brow][bc + 2] = to_tf32(v.z);
            Bs[brow][bc + 3] = to_tf32(v.w);
        }
        __syncthreads();

#pragma unroll
        for (int ks = 0; ks < 4; ks++) {
            int k = ks * 8;
            uint32_t a[2][4], b[4][2];
#pragma unroll
            for (int mi = 0; mi < 2; mi++) {
                int r0 = m_base + mi * 16 + (lane >> 2);
                int c0 = k + (lane & 3);
                a[mi][0] = __float_as_uint(As[r0][c0]);
                a[mi][1] = __float_as_uint(As[r0 + 8][c0]);
                a[mi][2] = __float_as_uint(As[r0][c0 + 4]);
                a[mi][3] = __float_as_uint(As[r0 + 8][c0 + 4]);
            }
#pragma unroll
            for (int ni = 0; ni < 4; ni++) {
                int col = n_base + ni * 8 + (lane >> 2);
                int kr  = k + (lane & 3);
                b[ni][0] = __float_as_uint(Bs[kr][col]);
                b[ni][1] = __float_as_uint(Bs[kr + 4][col]);
            }
#pragma unroll
            for (int mi = 0; mi < 2; mi++)
#pragma unroll
                for (int ni = 0; ni < 4; ni++) {
                    asm volatile(
                        "mma.sync.aligned.m16n8k8.row.col.f32.tf32.tf32.f32 "
                        "{%0,%1,%2,%3}, {%4,%5,%6,%7}, {%8,%9}, {%0,%1,%2,%3};\n"
                        : "+f"(acc[mi][ni][0]), "+f"(acc[mi][ni][1]),
                          "+f"(acc[mi][ni][2]), "+f"(acc[mi][ni][3])
                        : "r"(a[mi][0]), "r"(a[mi][1]), "r"(a[mi][2]), "r"(a[mi][3]),
                          "r"(b[ni][0]), "r"(b[ni][1]));
                }
        }
    }

    // epilogue: scale by router prob, scatter to original token rows
#pragma unroll
    for (int mi = 0; mi < 2; mi++) {
#pragma unroll
        for (int half = 0; half < 2; half++) {
            int row = m_base + mi * 16 + half * 8 + (lane >> 2);
            if (mt * BM + row < cnt) {
                int token = g_perm[base + row];
                float p = g_maxprob[token];
                float* op = out + (size_t)token * HH + n0;
#pragma unroll
                for (int ni = 0; ni < 4; ni++) {
                    int c = n_base + ni * 8 + (lane & 3) * 2;
                    op[c]     = acc[mi][ni][half * 2 + 0] * p;
                    op[c + 1] = acc[mi][ni][half * 2 + 1] * p;
                }
            }
        }
    }
}

extern "C" void kernel_launch(void* const* d_in, const int* in_sizes, int n_in,
                              void* d_out, int out_size) {
    const float* x  = (const float*)d_in[0];
    const float* Wr = (const float*)d_in[1];
    const float* br = (const float*)d_in[2];
    const float* W1 = (const float*)d_in[3];
    const float* W2 = (const float*)d_in[4];
    float* out = (float*)d_out;

    init_kernel<<<1, 32>>>();
    router_kernel<<<TT / 4, 128>>>(x, Wr, br);
    scan_kernel<<<1, 32>>>();
    perm_kernel<<<TT / 256, 256>>>();
    fc1_kernel<<<dim3(TILES_M * NE, FF / BN), 256>>>(x, W1);
    fc2_kernel<<<dim3(TILES_M * NE, HH / BN), 256>>>(W2, out);
}

// round 3
// speedup vs baseline: 1.3458x; 1.3458x over previous
#include <cuda_runtime.h>
#include <cstdint>

#define TT 4096   // tokens = B*S
#define HH 1024   // hidden
#define FF 4096   // ffn
#define NE 8      // experts

#define BM 128
#define BN 128
#define BK 32
#define STAGES 3
#define TILES_M (TT / BM)           // 32 per expert (worst case)
#define STAGE_BYTES 32768           // A 16KB + B 16KB
#define SMEM_BYTES (STAGES * STAGE_BYTES + 256)

// ---------------- scratch (static device globals; no runtime alloc) --------
__device__ float g_xg [(size_t)(TT + BM) * HH];   // gathered + tf32-rounded acts
__device__ float g_mid[(size_t)(TT + BM) * FF];   // fc1 out (perm order, tf32-rounded)
__device__ int   g_perm[TT];
__device__ int   g_expert_of[TT];
__device__ float g_maxprob[TT];
__device__ int   g_cnt[NE];
__device__ int   g_off[NE + 1];
__device__ int   g_cur[NE];

// ---------------- helpers ---------------------------------------------------
__device__ __forceinline__ uint32_t smem_u32(const void* p) {
    uint32_t a;
    asm("{ .reg .u64 t; cvta.to.shared.u64 t, %1; cvt.u32.u64 %0, t; }" : "=r"(a) : "l"(p));
    return a;
}
__device__ __forceinline__ float to_tf32(float x) {
    uint32_t u;
    asm("cvt.rna.tf32.f32 %0, %1;" : "=r"(u) : "f"(x));
    return __uint_as_float(u);
}
__device__ __forceinline__ uint32_t to_tf32_u(float x) {
    uint32_t u;
    asm("cvt.rna.tf32.f32 %0, %1;" : "=r"(u) : "f"(x));
    return u;
}
__device__ __forceinline__ float gelu_exact(float v) {
    return 0.5f * v * (1.0f + erff(v * 0.7071067811865476f));
}
__device__ __forceinline__ void cp_async16(uint32_t dst, const void* src) {
    asm volatile("cp.async.cg.shared.global [%0], [%1], 16;" :: "r"(dst), "l"(src));
}
__device__ __forceinline__ void cp_commit() {
    asm volatile("cp.async.commit_group;" ::: "memory");
}
template<int N>
__device__ __forceinline__ void cp_wait() {
    asm volatile("cp.async.wait_group %0;" :: "n"(N) : "memory");
}

// ---------------- routing kernels ------------------------------------------
__global__ void init_kernel() {
    if (threadIdx.x < NE) g_cnt[threadIdx.x] = 0;
}

__global__ void router_kernel(const float* __restrict__ x,
                              const float* __restrict__ Wr,
                              const float* __restrict__ br) {
    int warp = (blockIdx.x * blockDim.x + threadIdx.x) >> 5;
    int lane = threadIdx.x & 31;
    if (warp >= TT) return;
    const float* xr = x + (size_t)warp * HH;
    float acc[NE];
#pragma unroll
    for (int e = 0; e < NE; e++) acc[e] = 0.f;
    for (int i = lane; i < HH; i += 32) {
        float xv = xr[i];
        const float4* w4 = reinterpret_cast<const float4*>(Wr + i * NE);
        float4 w0 = w4[0], w1 = w4[1];
        acc[0] += xv * w0.x; acc[1] += xv * w0.y;
        acc[2] += xv * w0.z; acc[3] += xv * w0.w;
        acc[4] += xv * w1.x; acc[5] += xv * w1.y;
        acc[6] += xv * w1.z; acc[7] += xv * w1.w;
    }
#pragma unroll
    for (int e = 0; e < NE; e++) {
#pragma unroll
        for (int o = 16; o > 0; o >>= 1)
            acc[e] += __shfl_xor_sync(0xffffffffu, acc[e], o);
    }
    if (lane == 0) {
        float best = acc[0] + br[0]; int bi = 0;
#pragma unroll
        for (int e = 1; e < NE; e++) {
            float v = acc[e] + br[e];
            if (v > best) { best = v; bi = e; }
        }
        g_expert_of[warp] = bi;
        g_maxprob[warp]   = 1.0f / (1.0f + expf(-best));
        atomicAdd(&g_cnt[bi], 1);
    }
}

__global__ void scan_kernel() {
    if (threadIdx.x == 0) {
        int off = 0;
        for (int e = 0; e < NE; e++) {
            g_off[e] = off; g_cur[e] = off; off += g_cnt[e];
        }
        g_off[NE] = off;
    }
}

__global__ void perm_kernel() {
    int t = blockIdx.x * blockDim.x + threadIdx.x;
    if (t < TT) {
        int e = g_expert_of[t];
        int slot = atomicAdd(&g_cur[e], 1);
        g_perm[slot] = t;
    }
}

// gather x rows into perm order, tf32-rounded (one block per slot)
__global__ void gather_kernel(const float* __restrict__ x) {
    int slot = blockIdx.x;
    int tok  = g_perm[slot];
    const float4* src = reinterpret_cast<const float4*>(x + (size_t)tok * HH);
    float4* dst = reinterpret_cast<float4*>(g_xg + (size_t)slot * HH);
    int c = threadIdx.x;            // 256 threads, HH/4 = 256
    float4 v = src[c];
    v.x = to_tf32(v.x); v.y = to_tf32(v.y);
    v.z = to_tf32(v.z); v.w = to_tf32(v.w);
    dst[c] = v;
}

// ---------------- pipelined tf32 grouped GEMM ------------------------------
// FC1: g_mid = tf32( gelu( g_xg @ W1[e] ) )   K=HH, N over FF
// FC2: out   = ( g_mid @ W2[e] ) * p          K=FF, N over HH
//
// 256 threads, 8 warps (4 m x 2 n), warp tile 32x64, mma m16n8k8 tf32.
// Smem: A[128][32] 128B rows, chunk^(m&7) swizzle.
//       B[32][128] 512B rows, chunk^((k&3)<<1) swizzle.
template<int KTOT, bool FC2>
__global__ __launch_bounds__(256, 2)
void moe_gemm(const float* __restrict__ W, float* __restrict__ outp) {
    constexpr int LDB = FC2 ? HH : FF;
    constexpr int KIT = KTOT / BK;

    int e  = blockIdx.x >> 5;
    int mt = blockIdx.x & 31;
    int off0 = g_off[e];
    int cnt  = g_off[e + 1] - off0;
    if (mt * BM >= cnt) return;
    int base = off0 + mt * BM;
    int n0   = blockIdx.y * BN;
    const float* Be    = W + (size_t)e * KTOT * LDB;
    const float* Abase = (FC2 ? g_mid : g_xg) + (size_t)base * KTOT;

    extern __shared__ char smem_raw[];
    uint32_t s_u32 = smem_u32(smem_raw);
    uint32_t s0    = (s_u32 + 127u) & ~127u;
    char*    s_gen = smem_raw + (s0 - s_u32);

    int tid = threadIdx.x, lane = tid & 31, wid = tid >> 5;
    int g = lane >> 2, t = lane & 3;
    int wm = wid >> 1, wn = wid & 1;
    int r0  = wm * 32;
    int nb0 = wn * 64;

    // A loader: row m = tid>>1, chunks (tid&1)*4 .. +3
    int am = tid >> 1;
    int aj = (tid & 1) * 4;
    const float* Arow = Abase + (size_t)am * KTOT;
    uint32_t a_dst_base = s0 + (uint32_t)am * 128u;
    // B loader: row kr = tid>>3, chunks j+8c
    int kr = tid >> 3;
    int bj = tid & 7;
    const float* Brow0 = Be + (size_t)kr * LDB + n0;
    uint32_t b_dst_base = s0 + 16384u + (uint32_t)kr * 512u;
    uint32_t b_sw = (uint32_t)((kr & 3) << 1);

    float acc[2][8][4];
#pragma unroll
    for (int mi = 0; mi < 2; mi++)
#pragma unroll
        for (int ni = 0; ni < 8; ni++)
#pragma unroll
            for (int c = 0; c < 4; c++) acc[mi][ni][c] = 0.f;

    auto issue_load = [&](int it) {
        uint32_t sb = (uint32_t)((it % STAGES) * STAGE_BYTES);
        int kb = it * BK;
        const float* as = Arow + kb + aj * 4;
#pragma unroll
        for (int c = 0; c < 4; c++) {
            uint32_t ch = (uint32_t)(aj + c);
            cp_async16(a_dst_base + sb + ((ch ^ (uint32_t)(am & 7)) << 4), as + c * 4);
        }
        const float* bs = Brow0 + (size_t)kb * LDB;
#pragma unroll
        for (int c = 0; c < 4; c++) {
            uint32_t ch = (uint32_t)(bj + 8 * c);
            cp_async16(b_dst_base + sb + ((ch ^ b_sw) << 4), bs + ch * 4);
        }
    };

    // prologue: stages 0..S-2
#pragma unroll
    for (int s = 0; s < STAGES - 1; s++) {
        if (s < KIT) issue_load(s);
        cp_commit();
    }

    for (int it = 0; it < KIT; it++) {
        cp_wait<STAGES - 2>();
        __syncthreads();
        int nx = it + STAGES - 1;
        if (nx < KIT) issue_load(nx);
        cp_commit();

        char* sA = s_gen + (it % STAGES) * STAGE_BYTES;
        char* sB = sA + 16384;

#pragma unroll
        for (int ks = 0; ks < 4; ks++) {
            // ---- A fragments (pre-rounded tf32 in gmem) ----
            uint32_t a[2][4];
#pragma unroll
            for (int mi = 0; mi < 2; mi++) {
                int r = r0 + mi * 16 + g;          // r&7 == g
                char* rowp = sA + r * 128;
                uint32_t c0 = (uint32_t)((2 * ks) ^ g) << 4;
                uint32_t c1 = (uint32_t)((2 * ks + 1) ^ g) << 4;
                char* rowp8 = sA + (r + 8) * 128;
                uint32_t d0 = (uint32_t)((2 * ks) ^ (g ^ 0)) << 4;  // (r+8)&7 == g
                a[mi][0] = *(const uint32_t*)(rowp  + c0 + t * 4);
                a[mi][1] = *(const uint32_t*)(rowp8 + d0 + t * 4);
                a[mi][2] = *(const uint32_t*)(rowp  + c1 + t * 4);
                a[mi][3] = *(const uint32_t*)(rowp8 + c1 + t * 4);
            }
            // ---- B fragments (rounded RNE here) ----
            uint32_t b[8][2];
            char* bk0 = sB + (ks * 8 + t) * 512;
#pragma unroll
            for (int ni = 0; ni < 8; ni++) {
                uint32_t chn = (uint32_t)((nb0 >> 2) + 2 * ni + (g >> 2));
                uint32_t off = ((chn ^ (uint32_t)(t << 1)) << 4) + (uint32_t)(g & 3) * 4;
                float v0 = *(const float*)(bk0 + off);
                float v1 = *(const float*)(bk0 + 2048 + off);
                b[ni][0] = to_tf32_u(v0);
                b[ni][1] = to_tf32_u(v1);
            }
#pragma unroll
            for (int mi = 0; mi < 2; mi++)
#pragma unroll
                for (int ni = 0; ni < 8; ni++) {
                    asm volatile(
                        "mma.sync.aligned.m16n8k8.row.col.f32.tf32.tf32.f32 "
                        "{%0,%1,%2,%3}, {%4,%5,%6,%7}, {%8,%9}, {%0,%1,%2,%3};\n"
                        : "+f"(acc[mi][ni][0]), "+f"(acc[mi][ni][1]),
                          "+f"(acc[mi][ni][2]), "+f"(acc[mi][ni][3])
                        : "r"(a[mi][0]), "r"(a[mi][1]), "r"(a[mi][2]), "r"(a[mi][3]),
                          "r"(b[ni][0]), "r"(b[ni][1]));
                }
        }
    }

    // ---------------- epilogue ----------------
#pragma unroll
    for (int mi = 0; mi < 2; mi++) {
#pragma unroll
        for (int half = 0; half < 2; half++) {
            int row = r0 + mi * 16 + half * 8 + g;
            if (mt * BM + row >= cnt) continue;
            if (!FC2) {
                float* op = g_mid + (size_t)(base + row) * FF + n0;
#pragma unroll
                for (int ni = 0; ni < 8; ni++) {
                    float2 v;
                    v.x = to_tf32(gelu_exact(acc[mi][ni][half * 2 + 0]));
                    v.y = to_tf32(gelu_exact(acc[mi][ni][half * 2 + 1]));
                    *reinterpret_cast<float2*>(op + nb0 + ni * 8 + 2 * t) = v;
                }
            } else {
                int token = g_perm[base + row];
                float p = g_maxprob[token];
                float* op = outp + (size_t)token * HH + n0;
#pragma unroll
                for (int ni = 0; ni < 8; ni++) {
                    float2 v;
                    v.x = acc[mi][ni][half * 2 + 0] * p;
                    v.y = acc[mi][ni][half * 2 + 1] * p;
                    *reinterpret_cast<float2*>(op + nb0 + ni * 8 + 2 * t) = v;
                }
            }
        }
    }
}

// ---------------- launch ----------------------------------------------------
extern "C" void kernel_launch(void* const* d_in, const int* in_sizes, int n_in,
                              void* d_out, int out_size) {
    const float* x  = (const float*)d_in[0];
    const float* Wr = (const float*)d_in[1];
    const float* br = (const float*)d_in[2];
    const float* W1 = (const float*)d_in[3];
    const float* W2 = (const float*)d_in[4];
    float* out = (float*)d_out;

    static bool attr_done = false;
    if (!attr_done) {
        cudaFuncSetAttribute(moe_gemm<HH, false>,
                             cudaFuncAttributeMaxDynamicSharedMemorySize, SMEM_BYTES);
        cudaFuncSetAttribute(moe_gemm<FF, true>,
                             cudaFuncAttributeMaxDynamicSharedMemorySize, SMEM_BYTES);
        attr_done = true;
    }

    init_kernel<<<1, 32>>>();
    router_kernel<<<TT / 4, 128>>>(x, Wr, br);
    scan_kernel<<<1, 32>>>();
    perm_kernel<<<TT / 256, 256>>>();
    gather_kernel<<<TT, 256>>>(x);
    moe_gemm<HH, false><<<dim3(TILES_M * NE, FF / BN), 256, SMEM_BYTES>>>(W1, nullptr);
    moe_gemm<FF, true ><<<dim3(TILES_M * NE, HH / BN), 256, SMEM_BYTES>>>(W2, out);
}